// round 15
// baseline (speedup 1.0000x reference)
#include <cuda_runtime.h>
#include <cuda_fp16.h>
#include <cstdint>
#include <cstddef>

// ---------------------------------------------------------------------------
// SpikingTransformerBlock, mma.sync fp16 2-term path (base sm_100 compatible)
// R15: attn-input LIF folded into prep_all tail; fc2 on the 256-thr deep-K
// engine. 8 launches.
// ---------------------------------------------------------------------------

#define BB 4
#define CC 512
#define TT 4
#define NNv 512
#define LLv 2048
#define HIDN 2048
#define NH 8
#define HD 64
#define CQKV 1536
#define KVSPL 8

// ---- 128-thr GEMM config (proj) ----
#define MT 128
#define NTP 128
#define KCH 32
#define TERMS 2
#define A_TERM_BYTES (MT * KCH * 2)           // 8192
#define A_BYTES (TERMS * A_TERM_BYTES)        // 16384
#define B_BYTES (NTP * KCH * 2)               // 8192
#define STAGE_BYTES (A_BYTES + B_BYTES)       // 24576
#define NSTAGE 3
#define DYN_SMEM (NSTAGE * STAGE_BYTES)       // 73728

// ---- 256-thr GEMM config (qkv / fc1 / fc2) ----
#define KCB 64
#define ATB (MT * KCB * 2)                    // 16384
#define ABB (TERMS * ATB)                     // 32768
#define BBB (256 * KCB * 2)                   // 32768
#define STGB (ABB + BBB)                      // 65536
#define DSMB (3 * STGB)                       // 196608

#define SW(o) ((o) ^ (((o) >> 3) & 0x70))

#define SZ   (CC * CC)      // 262144
#define SZH  (HIDN * CC)    // 1048576
#define WSPLIT_BLOCKS ((4 * SZ + 2 * SZH) / 256)   // 12288
#define BN_BLOCKS 48
#define LIF_BLOCKS 1024                             // (16 n)(16 c)(4 b)

// -------------------- device scratch ---------------------------------------
__device__ __half g_skv[(size_t)BB * CQKV * LLv];
__device__ float g_x1 [(size_t)BB * CC * LLv];
__device__ float g_Mp [(size_t)KVSPL * BB * NH * HD * HD];
__device__ __half g_xqT[(size_t)BB * LLv * CC];
__device__ __half g_soT[(size_t)BB * LLv * CC];
__device__ __half g_s2T[(size_t)BB * LLv * HIDN];
__device__ __half g_w[8 * SZ + 4 * SZH];
__device__ float g_scale[6 * 2048];
__device__ float g_shift[6 * 2048];

// -------------------- helpers ----------------------------------------------
__device__ __forceinline__ uint32_t smem_u32(const void* p) {
    uint32_t a;
    asm("{ .reg .u64 t; cvta.to.shared.u64 t, %1; cvt.u32.u64 %0, t; }" : "=r"(a) : "l"(p));
    return a;
}
#define CP16(sa, gp) \
    asm volatile("cp.async.cg.shared.global [%0], [%1], 16;" :: "r"(sa), "l"(gp) : "memory")
#define CP_COMMIT() asm volatile("cp.async.commit_group;" ::: "memory")
#define CP_WAIT1() asm volatile("cp.async.wait_group 1;" ::: "memory")
#define CP_WAIT0() asm volatile("cp.async.wait_group 0;" ::: "memory")

__device__ __forceinline__ void ldm_x4(uint32_t& r0, uint32_t& r1, uint32_t& r2, uint32_t& r3,
                                       uint32_t addr) {
    asm volatile("ldmatrix.sync.aligned.m8n8.x4.shared.b16 {%0,%1,%2,%3}, [%4];"
                 : "=r"(r0), "=r"(r1), "=r"(r2), "=r"(r3) : "r"(addr));
}
__device__ __forceinline__ void mma16816(float* c, uint32_t a0, uint32_t a1, uint32_t a2,
                                         uint32_t a3, uint32_t b0, uint32_t b1) {
    asm volatile("mma.sync.aligned.m16n8k16.row.col.f32.f16.f16.f32 "
                 "{%0,%1,%2,%3},{%4,%5,%6,%7},{%8,%9},{%0,%1,%2,%3};"
                 : "+f"(c[0]), "+f"(c[1]), "+f"(c[2]), "+f"(c[3])
                 : "r"(a0), "r"(a1), "r"(a2), "r"(a3), "r"(b0), "r"(b1));
}

// -------------------- merged prologue: wsplit + BN folds + attn LIF ---------
__global__ void prep_all(const float* __restrict__ qw, const float* __restrict__ kw,
                         const float* __restrict__ vw, const float* __restrict__ pw,
                         const float* __restrict__ f1, const float* __restrict__ f2,
                         __half* __restrict__ wqkv, __half* __restrict__ wp,
                         __half* __restrict__ wf1, __half* __restrict__ wf2,
                         const float* __restrict__ p0, const float* __restrict__ p1,
                         const float* __restrict__ p2, const float* __restrict__ p3,
                         const float* __restrict__ p4, const float* __restrict__ p5,
                         const float* __restrict__ fc1b,
                         float* __restrict__ scale, float* __restrict__ shift,
                         const float* __restrict__ x, __half* __restrict__ xqT) {
    int bid = blockIdx.x;
    if (bid >= WSPLIT_BLOCKS + BN_BLOCKS) {
        // attn-input LIF tail (inline BN from p0)
        __shared__ float tile[TT][32][33];
        int rb = bid - WSPLIT_BLOCKS - BN_BLOCKS;
        int nb = rb & 15, cbk = (rb >> 4) & 15, b = rb >> 8;
        int tx = threadIdx.x & 31, ty = threadIdx.x >> 5;
        int c0 = cbk * 32, n0 = nb * 32;
#pragma unroll
        for (int i = 0; i < 4; ++i) {
            int c = c0 + ty + 8 * i;
            float g = p0[c], be = p0[CC + c], m = p0[2 * CC + c], va = p0[3 * CC + c];
            float inv = g / sqrtf(va + 1e-5f);
            float sh = be - m * inv;
            size_t base = ((size_t)b * CC + c) * LLv + n0 + tx;
            float v = 0.f;
#pragma unroll
            for (int t = 0; t < TT; ++t) {
                float xv = x[base + (size_t)t * NNv] * inv + sh;
                v += (xv - v) / 1.5f;
                float sp = (v >= 1.f) ? 1.f : 0.f;
                tile[t][ty + 8 * i][tx] = sp;
                v = (v >= 1.f) ? 0.f : v;
            }
        }
        __syncthreads();
#pragma unroll
        for (int t = 0; t < TT; ++t)
#pragma unroll
            for (int i = 0; i < 4; ++i) {
                int l = t * NNv + n0 + ty + 8 * i;
                xqT[((size_t)b * LLv + l) * CC + c0 + tx] =
                    __float2half_rn(tile[t][tx][ty + 8 * i]);
            }
        return;
    }
    if (bid >= WSPLIT_BLOCKS) {
        int rb = bid - WSPLIT_BLOCKS;
        int slot = rb >> 3;
        int Cdim = (slot == 5) ? 2048 : 512;
        int c = (rb & 7) * 256 + threadIdx.x;
        if (c >= Cdim) return;
        const float* p = (slot == 0) ? p0 : (slot == 1) ? p1 : (slot == 2) ? p2 :
                         (slot == 3) ? p3 : (slot == 4) ? p4 : p5;
        float g = p[c], be = p[Cdim + c], m = p[2 * Cdim + c], va = p[3 * Cdim + c];
        float inv = g / sqrtf(va + 1e-5f);
        float sh = be - m * inv;
        if (slot == 5) sh += fc1b[c] * inv;
        scale[slot * 2048 + c] = inv;
        shift[slot * 2048 + c] = sh;
        return;
    }
    int i = bid * 256 + threadIdx.x;
    const float* src; __half *dhi, *dlo;
    if (i < 3 * SZ) {
        int seg = i / SZ, j = i - seg * SZ;
        src = (seg == 0) ? qw + j : (seg == 1) ? kw + j : vw + j;
        dhi = wqkv + seg * SZ + j; dlo = wqkv + 3 * SZ + seg * SZ + j;
    } else if (i < 4 * SZ) {
        int j = i - 3 * SZ;
        src = pw + j; dhi = wp + j; dlo = wp + SZ + j;
    } else if (i < 4 * SZ + SZH) {
        int j = i - 4 * SZ;
        src = f1 + j; dhi = wf1 + j; dlo = wf1 + SZH + j;
    } else {
        int j = i - 4 * SZ - SZH;
        src = f2 + j; dhi = wf2 + j; dlo = wf2 + SZH + j;
    }
    float xv = *src;
    __half h = __float2half_rn(xv);
    *dhi = h;
    *dlo = __float2half_rn(xv - __half2float(h));
}

// -------------------- LIF + BN -> transposed fp16 spikes (mlp input) --------
__global__ void lif_tr_k(const float* __restrict__ in, __half* __restrict__ outT,
                         const float* __restrict__ scale, const float* __restrict__ shift,
                         int Cdim) {
    __shared__ float tile[TT][32][33];
    int b = blockIdx.z, c0 = blockIdx.y * 32, n0 = blockIdx.x * 32;
    int tx = threadIdx.x, ty = threadIdx.y;
#pragma unroll
    for (int i = 0; i < 4; ++i) {
        int c = c0 + ty + 8 * i;
        float sc = scale ? scale[c] : 1.f;
        float sh = shift ? shift[c] : 0.f;
        size_t base = ((size_t)b * Cdim + c) * LLv + n0 + tx;
        float v = 0.f;
#pragma unroll
        for (int t = 0; t < TT; ++t) {
            float xv = in[base + (size_t)t * NNv] * sc + sh;
            v += (xv - v) / 1.5f;
            float sp = (v >= 1.f) ? 1.f : 0.f;
            tile[t][ty + 8 * i][tx] = sp;
            v = (v >= 1.f) ? 0.f : v;
        }
    }
    __syncthreads();
#pragma unroll
    for (int t = 0; t < TT; ++t)
#pragma unroll
        for (int i = 0; i < 4; ++i) {
            int l = t * NNv + n0 + ty + 8 * i;
            outT[((size_t)b * LLv + l) * Cdim + c0 + tx] =
                __float2half_rn(tile[t][tx][ty + 8 * i]);
        }
}

// ================= 256-thr GEMM engine ======================================
#define GEMM256_PREAMBLE()                                                      \
    extern __shared__ __align__(16) char smem[];                                \
    uint32_t sb = smem_u32(smem);                                               \
    int tid = threadIdx.x;                                                      \
    int lane = tid & 31, w = tid >> 5;                                          \
    int wm = w & 1, wn = w >> 1;                                                \
    int sub = lane >> 3, lrow = lane & 7;                                       \
    float acc[4][8][4];                                                         \
    _Pragma("unroll")                                                           \
    for (int i = 0; i < 4; ++i)                                                 \
        _Pragma("unroll")                                                       \
        for (int j = 0; j < 8; ++j)                                             \
            _Pragma("unroll")                                                   \
            for (int r = 0; r < 4; ++r) acc[i][j][r] = 0.f;

#define ISSUE256_TMAJ(TERMSTRIDE)                                               \
    auto issue_loads = [&](int c) {                                             \
        uint32_t base = sb + (uint32_t)(c % 3) * STGB;                          \
        int k0 = c * KCB;                                                       \
        _Pragma("unroll")                                                       \
        for (int i = 0; i < 8; ++i) {                                           \
            int idx = i * 256 + tid;                                            \
            int term = idx >> 10;                                               \
            int within = idx & 1023;                                            \
            int row = within >> 3, c16 = within & 7;                            \
            uint32_t o = (uint32_t)(row * 128 + c16 * 16);                      \
            CP16(base + term * ATB + SW(o),                                     \
                 Wspl + (size_t)term * (TERMSTRIDE) +                           \
                 (size_t)(tm + row) * CC + k0 + c16 * 8);                       \
        }                                                                       \
        _Pragma("unroll")                                                       \
        for (int i = 0; i < 8; ++i) {                                           \
            int idx = i * 256 + tid;                                            \
            int ridx = idx >> 3, c16 = idx & 7;                                 \
            int t = ridx >> 6, nloc = ridx & 63;                                \
            int l = t * NNv + n0 + nloc;                                        \
            uint32_t o = (uint32_t)(ridx * 128 + c16 * 16);                     \
            CP16(base + ABB + SW(o),                                            \
                 Bt + (size_t)l * CC + k0 + c16 * 8);                           \
        }                                                                       \
        CP_COMMIT();                                                            \
    };

#define ISSUE256_PLAIN(TERMSTRIDE, CI)                                          \
    auto issue_loads = [&](int c) {                                             \
        uint32_t base = sb + (uint32_t)(c % 3) * STGB;                          \
        int k0 = c * KCB;                                                       \
        _Pragma("unroll")                                                       \
        for (int i = 0; i < 8; ++i) {                                           \
            int idx = i * 256 + tid;                                            \
            int term = idx >> 10;                                               \
            int within = idx & 1023;                                            \
            int row = within >> 3, c16 = within & 7;                            \
            uint32_t o = (uint32_t)(row * 128 + c16 * 16);                      \
            CP16(base + term * ATB + SW(o),                                     \
                 Wspl + (size_t)term * (TERMSTRIDE) +                           \
                 (size_t)(tm + row) * (CI) + k0 + c16 * 8);                     \
        }                                                                       \
        _Pragma("unroll")                                                       \
        for (int i = 0; i < 8; ++i) {                                           \
            int idx = i * 256 + tid;                                            \
            int ridx = idx >> 3, c16 = idx & 7;                                 \
            uint32_t o = (uint32_t)(ridx * 128 + c16 * 16);                     \
            CP16(base + ABB + SW(o),                                            \
                 Bt + (size_t)(tn + ridx) * (CI) + k0 + c16 * 8);               \
        }                                                                       \
        CP_COMMIT();                                                            \
    };

#define GEMM256_MAINLOOP()                                                      \
    issue_loads(0);                                                             \
    issue_loads(1);                                                             \
    for (int c = 0; c < KC; ++c) {                                              \
        uint32_t base = sb + (uint32_t)(c % 3) * STGB;                          \
        if (c < KC - 1) CP_WAIT1(); else CP_WAIT0();                            \
        __syncthreads();                                                        \
        if (c + 2 < KC) issue_loads(c + 2);                                     \
        uint32_t abase = base;                                                  \
        uint32_t bbase = base + ABB;                                            \
        _Pragma("unroll")                                                       \
        for (int ks = 0; ks < 4; ++ks) {                                        \
            uint32_t bfr[4][4];                                                 \
            _Pragma("unroll")                                                   \
            for (int t = 0; t < 4; ++t) {                                       \
                int rbase = t * 64 + wn * 16 + (sub >> 1) * 8 + lrow;           \
                uint32_t o = (uint32_t)(rbase * 128 + ks * 32 + (sub & 1) * 16);\
                ldm_x4(bfr[t][0], bfr[t][1], bfr[t][2], bfr[t][3],              \
                       bbase + SW(o));                                          \
            }                                                                   \
            _Pragma("unroll")                                                   \
            for (int term = 0; term < TERMS; ++term) {                          \
                uint32_t tb = abase + term * ATB;                               \
                uint32_t af[4][4];                                              \
                _Pragma("unroll")                                               \
                for (int mi = 0; mi < 4; ++mi) {                                \
                    int m = wm * 64 + mi * 16 + (sub & 1) * 8 + lrow;           \
                    uint32_t o = (uint32_t)(m * 128 + ks * 32 + (sub >> 1) * 16);\
                    ldm_x4(af[mi][0], af[mi][1], af[mi][2], af[mi][3],          \
                           tb + SW(o));                                         \
                }                                                               \
                _Pragma("unroll")                                               \
                for (int mi = 0; mi < 4; ++mi)                                  \
                    _Pragma("unroll")                                           \
                    for (int nj = 0; nj < 8; ++nj)                              \
                        mma16816(acc[mi][nj], af[mi][0], af[mi][1], af[mi][2],  \
                                 af[mi][3], bfr[nj >> 1][(nj & 1) * 2],         \
                                 bfr[nj >> 1][(nj & 1) * 2 + 1]);               \
            }                                                                   \
        }                                                                       \
    }

// -------------------- fused qkv GEMM + BN + LIF -> skv fp16 -----------------
__global__ void __launch_bounds__(256, 1) gemm_qkv_k(
    const __half* __restrict__ Wspl, const __half* __restrict__ BT,
    __half* __restrict__ out, const float* __restrict__ scale,
    const float* __restrict__ shift) {

    GEMM256_PREAMBLE();
    int b = blockIdx.z;
    int tm = blockIdx.y * MT;
    int n0 = blockIdx.x * 64;
    const __half* Bt = BT + (size_t)b * LLv * CC;
    const int KC = CC / KCB;   // 8
    ISSUE256_TMAJ((size_t)CQKV * CC);
    GEMM256_MAINLOOP();

#pragma unroll
    for (int mi = 0; mi < 4; ++mi) {
#pragma unroll
        for (int h = 0; h < 2; ++h) {
            int co = tm + wm * 64 + mi * 16 + h * 8 + (lane >> 2);
            int sidx = ((co >> 9) << 11) | (co & 511);
            float scv = scale[sidx], shv = shift[sidx];
            __half* op = out + ((size_t)b * CQKV + co) * LLv;
#pragma unroll
            for (int uh = 0; uh < 2; ++uh) {
                float v0 = 0.f, v1 = 0.f;
#pragma unroll
                for (int t = 0; t < 4; ++t) {
                    int nj = t * 2 + uh;
                    float x0 = acc[mi][nj][h * 2 + 0] * scv + shv;
                    float x1 = acc[mi][nj][h * 2 + 1] * scv + shv;
                    v0 += (x0 - v0) / 1.5f;
                    float s0 = (v0 >= 1.f) ? 1.f : 0.f; v0 = (v0 >= 1.f) ? 0.f : v0;
                    v1 += (x1 - v1) / 1.5f;
                    float s1 = (v1 >= 1.f) ? 1.f : 0.f; v1 = (v1 >= 1.f) ? 0.f : v1;
                    int l = t * NNv + n0 + wn * 16 + uh * 8 + (lane & 3) * 2;
                    *(__half2*)(op + l) = __floats2half2_rn(s0, s1);
                }
            }
        }
    }
}

// -------------------- fused fc1 GEMM + BN + LIF -> s2T fp16 -----------------
__global__ void __launch_bounds__(256, 1) gemm_fc1_k(
    const __half* __restrict__ Wspl, const __half* __restrict__ BT,
    __half* __restrict__ s2T, const float* __restrict__ scale,
    const float* __restrict__ shift) {

    GEMM256_PREAMBLE();
    int b = blockIdx.z;
    int tm = blockIdx.y * MT;
    int n0 = blockIdx.x * 64;
    const __half* Bt = BT + (size_t)b * LLv * CC;
    const int KC = CC / KCB;   // 8
    ISSUE256_TMAJ((size_t)HIDN * CC);
    GEMM256_MAINLOOP();

    __syncthreads();
    __half* st = (__half*)smem;
#pragma unroll
    for (int mi = 0; mi < 4; ++mi) {
#pragma unroll
        for (int h = 0; h < 2; ++h) {
            int col = wm * 64 + mi * 16 + h * 8 + (lane >> 2);
            int co = tm + col;
            float scv = scale[co], shv = shift[co];
#pragma unroll
            for (int uh = 0; uh < 2; ++uh) {
                float v0 = 0.f, v1 = 0.f;
#pragma unroll
                for (int t = 0; t < 4; ++t) {
                    int nj = t * 2 + uh;
                    float x0 = acc[mi][nj][h * 2 + 0] * scv + shv;
                    float x1 = acc[mi][nj][h * 2 + 1] * scv + shv;
                    v0 += (x0 - v0) / 1.5f;
                    float s0 = (v0 >= 1.f) ? 1.f : 0.f; v0 = (v0 >= 1.f) ? 0.f : v0;
                    v1 += (x1 - v1) / 1.5f;
                    float s1 = (v1 >= 1.f) ? 1.f : 0.f; v1 = (v1 >= 1.f) ? 0.f : v1;
                    int ridx = t * 64 + wn * 16 + uh * 8 + (lane & 3) * 2;
                    st[ridx * 128 + col] = __float2half_rn(s0);
                    st[(ridx + 1) * 128 + col] = __float2half_rn(s1);
                }
            }
        }
    }
    __syncthreads();
    for (int i = tid; i < 256 * 16; i += 256) {
        int row = i >> 4, ch = i & 15;
        int t = row >> 6, nloc = row & 63;
        int l = t * NNv + n0 + nloc;
        uint4 v = *(uint4*)&st[row * 128 + ch * 8];
        *(uint4*)(s2T + ((size_t)b * LLv + l) * HIDN + tm + ch * 8) = v;
    }
}

// -------------------- fc2 GEMM (256-thr, Ci=2048) + bias + residual ---------
__global__ void __launch_bounds__(256, 1) gemm_fc2_k(
    const __half* __restrict__ Wspl, const __half* __restrict__ BT,
    float* __restrict__ out, const float* __restrict__ bias,
    const float* __restrict__ resid) {

    GEMM256_PREAMBLE();
    int b = blockIdx.z;
    int tm = blockIdx.y * MT;
    int tn = blockIdx.x * 256;
    const __half* Bt = BT + (size_t)b * LLv * HIDN;
    const int KC = HIDN / KCB;   // 32
    ISSUE256_PLAIN((size_t)CC * HIDN, HIDN);
    GEMM256_MAINLOOP();

#pragma unroll
    for (int mi = 0; mi < 4; ++mi) {
#pragma unroll
        for (int h = 0; h < 2; ++h) {
            int co = tm + wm * 64 + mi * 16 + h * 8 + (lane >> 2);
            float shv = bias[co];
            float* op = out + ((size_t)b * CC + co) * LLv + tn;
            const float* rp = resid + ((size_t)b * CC + co) * LLv + tn;
#pragma unroll
            for (int nj = 0; nj < 8; ++nj) {
                int col = (nj >> 1) * 64 + wn * 16 + (nj & 1) * 8 + (lane & 3) * 2;
                float2 rv = *(const float2*)(rp + col);
                float2 o;
                o.x = acc[mi][nj][h * 2 + 0] + shv + rv.x;
                o.y = acc[mi][nj][h * 2 + 1] + shv + rv.y;
                *(float2*)(op + col) = o;
            }
        }
    }
}

// ================= 128-thr GEMM (proj) ======================================
#define GEMM_MAINLOOP()                                                         \
    issue_loads(0);                                                             \
    issue_loads(1);                                                             \
    for (int c = 0; c < KC; ++c) {                                              \
        uint32_t base = sb + (uint32_t)(c % NSTAGE) * STAGE_BYTES;              \
        if (c < KC - 1) CP_WAIT1(); else CP_WAIT0();                            \
        __syncthreads();                                                        \
        if (c + 2 < KC) issue_loads(c + 2);                                     \
        uint32_t abase = base;                                                  \
        uint32_t bbase = base + A_BYTES;                                        \
        _Pragma("unroll")                                                       \
        for (int ks = 0; ks < 2; ++ks) {                                        \
            uint32_t bfr[4][4];                                                 \
            _Pragma("unroll")                                                   \
            for (int ni = 0; ni < 4; ++ni) {                                    \
                int n = wn * 64 + ni * 16 + (sub >> 1) * 8 + lrow;              \
                uint32_t o = (uint32_t)(n * 64 + ks * 32 + (sub & 1) * 16);     \
                ldm_x4(bfr[ni][0], bfr[ni][1], bfr[ni][2], bfr[ni][3],          \
                       bbase + SW(o));                                          \
            }                                                                   \
            _Pragma("unroll")                                                   \
            for (int term = 0; term < TERMS; ++term) {                          \
                uint32_t tb = abase + term * A_TERM_BYTES;                      \
                uint32_t af[4][4];                                              \
                _Pragma("unroll")                                               \
                for (int mi = 0; mi < 4; ++mi) {                                \
                    int m = wm * 64 + mi * 16 + (sub & 1) * 8 + lrow;           \
                    uint32_t o = (uint32_t)(m * 64 + ks * 32 + (sub >> 1) * 16);\
                    ldm_x4(af[mi][0], af[mi][1], af[mi][2], af[mi][3],          \
                           tb + SW(o));                                         \
                }                                                               \
                _Pragma("unroll")                                               \
                for (int mi = 0; mi < 4; ++mi)                                  \
                    _Pragma("unroll")                                           \
                    for (int nj = 0; nj < 8; ++nj)                              \
                        mma16816(acc[mi][nj], af[mi][0], af[mi][1], af[mi][2],  \
                                 af[mi][3], bfr[nj >> 1][(nj & 1) * 2],         \
                                 bfr[nj >> 1][(nj & 1) * 2 + 1]);               \
            }                                                                   \
        }                                                                       \
    }

__global__ void __launch_bounds__(128, 2) gemm_mma_k(
    const __half* __restrict__ Wspl, const __half* __restrict__ BT,
    float* __restrict__ out, const float* __restrict__ scale, const float* __restrict__ shift,
    const float* __restrict__ resid, int Co, int Ci) {

    extern __shared__ __align__(16) char smem[];
    uint32_t sb = smem_u32(smem);
    int tid = threadIdx.x;
    int lane = tid & 31, w = tid >> 5;
    int wm = w & 1, wn = w >> 1;
    int sub = lane >> 3, lrow = lane & 7;
    float acc[4][8][4];
#pragma unroll
    for (int i = 0; i < 4; ++i)
#pragma unroll
        for (int j = 0; j < 8; ++j)
#pragma unroll
            for (int r = 0; r < 4; ++r) acc[i][j][r] = 0.f;

    int b = blockIdx.z;
    int tm = blockIdx.y * MT;
    int tn = blockIdx.x * NTP;
    const __half* Bt = BT + (size_t)b * LLv * Ci;
    const size_t termstride = (size_t)Co * Ci;
    const int KC = Ci / KCH;

    auto issue_loads = [&](int c) {
        uint32_t base = sb + (uint32_t)(c % NSTAGE) * STAGE_BYTES;
        int k0 = c * KCH;
#pragma unroll
        for (int i = 0; i < 8; ++i) {
            int idx = i * 128 + tid;
            int term = idx >> 9;
            int within = idx & 511;
            int row = within >> 2, c16 = within & 3;
            uint32_t o = (uint32_t)(row * 64 + c16 * 16);
            CP16(base + term * A_TERM_BYTES + SW(o),
                 Wspl + (size_t)term * termstride + (size_t)(tm + row) * Ci + k0 + c16 * 8);
        }
#pragma unroll
        for (int i = 0; i < 4; ++i) {
            int idx = i * 128 + tid;
            int ridx = idx >> 2, c16 = idx & 3;
            uint32_t o = (uint32_t)(ridx * 64 + c16 * 16);
            CP16(base + A_BYTES + SW(o),
                 Bt + (size_t)(tn + ridx) * Ci + k0 + c16 * 8);
        }
        CP_COMMIT();
    };

    GEMM_MAINLOOP();

#pragma unroll
    for (int mi = 0; mi < 4; ++mi) {
#pragma unroll
        for (int h = 0; h < 2; ++h) {
            int co = tm + wm * 64 + mi * 16 + h * 8 + (lane >> 2);
            float scv = scale ? scale[co] : 1.f;
            float shv = shift ? shift[co] : 0.f;
            float* op = out + ((size_t)b * Co + co) * LLv + tn;
            const float* rp = resid ? resid + ((size_t)b * Co + co) * LLv + tn : nullptr;
#pragma unroll
            for (int nj = 0; nj < 8; ++nj) {
                int col = wn * 64 + nj * 8 + (lane & 3) * 2;
                float2 o;
                o.x = acc[mi][nj][h * 2 + 0] * scv + shv;
                o.y = acc[mi][nj][h * 2 + 1] * scv + shv;
                if (rp) {
                    float2 rv = *(const float2*)(rp + col);
                    o.x += rv.x; o.y += rv.y;
                }
                *(float2*)(op + col) = o;
            }
        }
    }
}

// -------------------- kv partials via tensor cores --------------------------
__global__ void __launch_bounds__(128, 2) kv_mma_k(
    const __half* __restrict__ skv, float* __restrict__ Mp) {
    __shared__ __align__(16) char smem[2 * 16384];
    uint32_t sb = smem_u32(smem);
    int tid = threadIdx.x;
    int lane = tid & 31, w = tid >> 5;
    int wm = w & 1, wn = w >> 1;
    int sub = lane >> 3, lrow = lane & 7;
    int bh = blockIdx.x, spl = blockIdx.y;
    int b = bh >> 3, h = bh & 7;
    const __half* K = skv + ((size_t)b * CQKV + 512 + h * HD) * LLv;
    const __half* V = skv + ((size_t)b * CQKV + 1024 + h * HD) * LLv;
    int lbeg = spl * (LLv / KVSPL);
    const int NCH = (LLv / KVSPL) / 64;

    float acc[2][4][4];
#pragma unroll
    for (int i = 0; i < 2; ++i)
#pragma unroll
        for (int j = 0; j < 4; ++j)
#pragma unroll
            for (int r = 0; r < 4; ++r) acc[i][j][r] = 0.f;

    auto issue = [&](int c) {
        uint32_t base = sb + (uint32_t)(c & 1) * 16384;
        int l0 = lbeg + c * 64;
#pragma unroll
        for (int i = 0; i < 8; ++i) {
            int idx = i * 128 + tid;
            int op = idx >> 9;
            int within = idx & 511;
            int row = within >> 3, c16 = within & 7;
            uint32_t o = (uint32_t)(row * 128 + c16 * 16);
            const __half* src = (op ? V : K) + (size_t)row * LLv + l0 + c16 * 8;
            CP16(base + op * 8192 + SW(o), src);
        }
        CP_COMMIT();
    };

    issue(0);
    issue(1);
    for (int c = 0; c < NCH; ++c) {
        uint32_t base = sb + (uint32_t)(c & 1) * 16384;
        if (c < NCH - 1) CP_WAIT1(); else CP_WAIT0();
        __syncthreads();
        uint32_t kbase = base, vbase = base + 8192;
#pragma unroll
        for (int ks = 0; ks < 4; ++ks) {
            uint32_t bfr[2][4];
#pragma unroll
            for (int ni = 0; ni < 2; ++ni) {
                int n = wn * 32 + ni * 16 + (sub >> 1) * 8 + lrow;
                uint32_t o = (uint32_t)(n * 128 + ks * 32 + (sub & 1) * 16);
                ldm_x4(bfr[ni][0], bfr[ni][1], bfr[ni][2], bfr[ni][3], vbase + SW(o));
            }
            uint32_t af[2][4];
#pragma unroll
            for (int mi = 0; mi < 2; ++mi) {
                int m = wm * 32 + mi * 16 + (sub & 1) * 8 + lrow;
                uint32_t o = (uint32_t)(m * 128 + ks * 32 + (sub >> 1) * 16);
                ldm_x4(af[mi][0], af[mi][1], af[mi][2], af[mi][3], kbase + SW(o));
            }
#pragma unroll
            for (int mi = 0; mi < 2; ++mi)
#pragma unroll
                for (int nj = 0; nj < 4; ++nj)
                    mma16816(acc[mi][nj], af[mi][0], af[mi][1], af[mi][2], af[mi][3],
                             bfr[nj >> 1][(nj & 1) * 2], bfr[nj >> 1][(nj & 1) * 2 + 1]);
        }
        __syncthreads();
        if (c + 2 < NCH) issue(c + 2);
    }

    float* Mo = Mp + ((size_t)spl * 32 + bh) * (HD * HD);
#pragma unroll
    for (int mi = 0; mi < 2; ++mi)
#pragma unroll
        for (int hh = 0; hh < 2; ++hh) {
            int j = wm * 32 + mi * 16 + hh * 8 + (lane >> 2);
#pragma unroll
            for (int nj = 0; nj < 4; ++nj) {
                int jp = wn * 32 + nj * 8 + (lane & 3) * 2;
                float2 o; o.x = acc[mi][nj][hh * 2 + 0]; o.y = acc[mi][nj][hh * 2 + 1];
                *(float2*)&Mo[j * HD + jp] = o;
            }
        }
}

// -------------------- o = q @ (sum Mp) via firing bitmask -------------------
__global__ void __launch_bounds__(256) qm_spike_k(
    const __half* __restrict__ skv, const float* __restrict__ Mp, __half* __restrict__ soT) {
    int bh = blockIdx.y;
    int b = bh >> 3, h = bh & 7;
    int l = blockIdx.x * 256 + threadIdx.x;
    __shared__ float Ms[HD * 65];
#pragma unroll
    for (int u = 0; u < 16; ++u) {
        int idx = u * 256 + threadIdx.x;
        float s = 0.f;
#pragma unroll
        for (int sp = 0; sp < KVSPL; ++sp)
            s += Mp[((size_t)sp * 32 + bh) * (HD * HD) + idx];
        Ms[(idx >> 6) * 65 + (idx & 63)] = s;
    }
    __syncthreads();
    const __half* Q = skv + ((size_t)b * CQKV + h * HD) * LLv + l;
    unsigned long long mask = 0;
#pragma unroll
    for (int j = 0; j < HD; ++j)
        if (__half2float(Q[(size_t)j * LLv]) > 0.5f) mask |= (1ull << j);

    float acc[HD];
#pragma unroll
    for (int jp = 0; jp < HD; ++jp) acc[jp] = 0.f;
    while (mask) {
        int j = __ffsll((long long)mask) - 1;
        mask &= mask - 1;
        const float* row = &Ms[j * 65];
#pragma unroll
        for (int jp = 0; jp < HD; ++jp) acc[jp] += row[jp];
    }
    __half* O = soT + ((size_t)b * LLv + l) * CC + h * HD;
#pragma unroll
    for (int jp = 0; jp < HD; ++jp) {
        float o = acc[jp] * 0.125f;
        O[jp] = __float2half_rn(((o / 1.5f - 1.f) >= 0.f) ? 1.f : 0.f);
    }
}

// ---------------------------------------------------------------------------
extern "C" void kernel_launch(void* const* d_in, const int* in_sizes, int n_in,
                              void* d_out, int out_size) {
    const float* x       = (const float*)d_in[0];
    const float* attn_bn = (const float*)d_in[1];
    const float* q_w     = (const float*)d_in[2];
    const float* q_bn    = (const float*)d_in[3];
    const float* k_w     = (const float*)d_in[4];
    const float* k_bn    = (const float*)d_in[5];
    const float* v_w     = (const float*)d_in[6];
    const float* v_bn    = (const float*)d_in[7];
    const float* proj_w  = (const float*)d_in[8];
    const float* proj_b  = (const float*)d_in[9];
    const float* mlp_bn  = (const float*)d_in[10];
    const float* fc1_w   = (const float*)d_in[11];
    const float* fc1_b   = (const float*)d_in[12];
    const float* fc1_bn  = (const float*)d_in[13];
    const float* fc2_w   = (const float*)d_in[14];
    const float* fc2_b   = (const float*)d_in[15];
    float* out = (float*)d_out;

    float *x1, *Mp, *scale, *shift;
    __half *skv, *xqT, *soT, *s2T, *w;
    cudaGetSymbolAddress((void**)&skv, g_skv);
    cudaGetSymbolAddress((void**)&x1,  g_x1);
    cudaGetSymbolAddress((void**)&Mp,  g_Mp);
    cudaGetSymbolAddress((void**)&scale, g_scale);
    cudaGetSymbolAddress((void**)&shift, g_shift);
    cudaGetSymbolAddress((void**)&xqT, g_xqT);
    cudaGetSymbolAddress((void**)&soT, g_soT);
    cudaGetSymbolAddress((void**)&s2T, g_s2T);
    cudaGetSymbolAddress((void**)&w,   g_w);

    cudaFuncSetAttribute(gemm_mma_k, cudaFuncAttributeMaxDynamicSharedMemorySize, DYN_SMEM);
    cudaFuncSetAttribute(gemm_qkv_k, cudaFuncAttributeMaxDynamicSharedMemorySize, DSMB);
    cudaFuncSetAttribute(gemm_fc1_k, cudaFuncAttributeMaxDynamicSharedMemorySize, DSMB);
    cudaFuncSetAttribute(gemm_fc2_k, cudaFuncAttributeMaxDynamicSharedMemorySize, DSMB);

    __half* wqkv = w;                       // [2][1536][512]
    __half* wp   = w + 6 * (size_t)SZ;      // [2][512][512]
    __half* wf1  = w + 8 * (size_t)SZ;      // [2][2048][512]
    __half* wf2  = wf1 + 2 * (size_t)SZH;   // [2][512][2048]

    // prologue: weight splits + BN folds + attn-input LIF (one launch)
    prep_all<<<WSPLIT_BLOCKS + BN_BLOCKS + LIF_BLOCKS, 256>>>(
        q_w, k_w, v_w, proj_w, fc1_w, fc2_w, wqkv, wp, wf1, wf2,
        attn_bn, q_bn, k_bn, v_bn, mlp_bn, fc1_bn, fc1_b, scale, shift,
        x, xqT);

    // fused q/k/v GEMM + BN + LIF -> skv spikes fp16 [B,1536,L]
    gemm_qkv_k<<<dim3(8, 12, 4), 256, DSMB>>>(wqkv, xqT, skv,
                                              scale + 2048, shift + 2048);

    // attention: exact q (k^T v) with tensor-core kv partials + bitmask qm
    kv_mma_k<<<dim3(32, KVSPL), 128>>>(skv, Mp);
    qm_spike_k<<<dim3(8, 32), 256>>>(skv, Mp, soT);

    // proj + residual -> x1
    gemm_mma_k<<<dim3(16, 4, 4), 128, DYN_SMEM>>>(wp, soT, x1, nullptr, proj_b, x, CC, CC);

    // MLP: BN+LIF -> xqT, fc1 fused -> s2T fp16, fc2 + bias + residual -> out
    lif_tr_k<<<dim3(16, 16, BB), dim3(32, 8)>>>(x1, xqT, scale + 4 * 2048,
                                                shift + 4 * 2048, CC);
    gemm_fc1_k<<<dim3(8, 16, 4), 256, DSMB>>>(wf1, xqT, s2T,
                                              scale + 5 * 2048, shift + 5 * 2048);
    gemm_fc2_k<<<dim3(8, 4, 4), 256, DSMB>>>(wf2, s2T, out, fc2_b, x1);
}

// round 16
// speedup vs baseline: 1.0682x; 1.0682x over previous
#include <cuda_runtime.h>
#include <cuda_fp16.h>
#include <cstdint>
#include <cstddef>

// ---------------------------------------------------------------------------
// SpikingTransformerBlock, mma.sync fp16 2-term path (base sm_100 compatible)
// R16: qm on tensor cores (ldmatrix.trans A, fp16 M^T, integer-exact);
// red_k reduces kv partials. 9 launches.
// ---------------------------------------------------------------------------

#define BB 4
#define CC 512
#define TT 4
#define NNv 512
#define LLv 2048
#define HIDN 2048
#define NH 8
#define HD 64
#define CQKV 1536
#define KVSPL 8

// ---- 128-thr GEMM config (proj) ----
#define MT 128
#define NTP 128
#define KCH 32
#define TERMS 2
#define A_TERM_BYTES (MT * KCH * 2)           // 8192
#define A_BYTES (TERMS * A_TERM_BYTES)        // 16384
#define B_BYTES (NTP * KCH * 2)               // 8192
#define STAGE_BYTES (A_BYTES + B_BYTES)       // 24576
#define NSTAGE 3
#define DYN_SMEM (NSTAGE * STAGE_BYTES)       // 73728

// ---- 256-thr GEMM config (qkv / fc1 / fc2) ----
#define KCB 64
#define ATB (MT * KCB * 2)                    // 16384
#define ABB (TERMS * ATB)                     // 32768
#define BBB (256 * KCB * 2)                   // 32768
#define STGB (ABB + BBB)                      // 65536
#define DSMB (3 * STGB)                       // 196608

#define SW(o) ((o) ^ (((o) >> 3) & 0x70))

#define SZ   (CC * CC)      // 262144
#define SZH  (HIDN * CC)    // 1048576
#define WSPLIT_BLOCKS ((4 * SZ + 2 * SZH) / 256)   // 12288
#define BN_BLOCKS 48
#define LIF_BLOCKS 1024

// -------------------- device scratch ---------------------------------------
__device__ __half g_skv[(size_t)BB * CQKV * LLv];
__device__ float g_x1 [(size_t)BB * CC * LLv];
__device__ float g_Mp [(size_t)KVSPL * BB * NH * HD * HD];
__device__ __half g_Mt [(size_t)BB * NH * HD * HD];      // M^T fp16 [bh][jp][j]
__device__ __half g_xqT[(size_t)BB * LLv * CC];
__device__ __half g_soT[(size_t)BB * LLv * CC];
__device__ __half g_s2T[(size_t)BB * LLv * HIDN];
__device__ __half g_w[8 * SZ + 4 * SZH];
__device__ float g_scale[6 * 2048];
__device__ float g_shift[6 * 2048];

// -------------------- helpers ----------------------------------------------
__device__ __forceinline__ uint32_t smem_u32(const void* p) {
    uint32_t a;
    asm("{ .reg .u64 t; cvta.to.shared.u64 t, %1; cvt.u32.u64 %0, t; }" : "=r"(a) : "l"(p));
    return a;
}
#define CP16(sa, gp) \
    asm volatile("cp.async.cg.shared.global [%0], [%1], 16;" :: "r"(sa), "l"(gp) : "memory")
#define CP_COMMIT() asm volatile("cp.async.commit_group;" ::: "memory")
#define CP_WAIT1() asm volatile("cp.async.wait_group 1;" ::: "memory")
#define CP_WAIT0() asm volatile("cp.async.wait_group 0;" ::: "memory")

__device__ __forceinline__ void ldm_x4(uint32_t& r0, uint32_t& r1, uint32_t& r2, uint32_t& r3,
                                       uint32_t addr) {
    asm volatile("ldmatrix.sync.aligned.m8n8.x4.shared.b16 {%0,%1,%2,%3}, [%4];"
                 : "=r"(r0), "=r"(r1), "=r"(r2), "=r"(r3) : "r"(addr));
}
__device__ __forceinline__ void ldm_x4t(uint32_t& r0, uint32_t& r1, uint32_t& r2, uint32_t& r3,
                                        uint32_t addr) {
    asm volatile("ldmatrix.sync.aligned.m8n8.x4.trans.shared.b16 {%0,%1,%2,%3}, [%4];"
                 : "=r"(r0), "=r"(r1), "=r"(r2), "=r"(r3) : "r"(addr));
}
__device__ __forceinline__ void mma16816(float* c, uint32_t a0, uint32_t a1, uint32_t a2,
                                         uint32_t a3, uint32_t b0, uint32_t b1) {
    asm volatile("mma.sync.aligned.m16n8k16.row.col.f32.f16.f16.f32 "
                 "{%0,%1,%2,%3},{%4,%5,%6,%7},{%8,%9},{%0,%1,%2,%3};"
                 : "+f"(c[0]), "+f"(c[1]), "+f"(c[2]), "+f"(c[3])
                 : "r"(a0), "r"(a1), "r"(a2), "r"(a3), "r"(b0), "r"(b1));
}

// -------------------- merged prologue: wsplit + BN folds + attn LIF ---------
__global__ void prep_all(const float* __restrict__ qw, const float* __restrict__ kw,
                         const float* __restrict__ vw, const float* __restrict__ pw,
                         const float* __restrict__ f1, const float* __restrict__ f2,
                         __half* __restrict__ wqkv, __half* __restrict__ wp,
                         __half* __restrict__ wf1, __half* __restrict__ wf2,
                         const float* __restrict__ p0, const float* __restrict__ p1,
                         const float* __restrict__ p2, const float* __restrict__ p3,
                         const float* __restrict__ p4, const float* __restrict__ p5,
                         const float* __restrict__ fc1b,
                         float* __restrict__ scale, float* __restrict__ shift,
                         const float* __restrict__ x, __half* __restrict__ xqT) {
    int bid = blockIdx.x;
    if (bid >= WSPLIT_BLOCKS + BN_BLOCKS) {
        __shared__ float tile[TT][32][33];
        int rb = bid - WSPLIT_BLOCKS - BN_BLOCKS;
        int nb = rb & 15, cbk = (rb >> 4) & 15, b = rb >> 8;
        int tx = threadIdx.x & 31, ty = threadIdx.x >> 5;
        int c0 = cbk * 32, n0 = nb * 32;
#pragma unroll
        for (int i = 0; i < 4; ++i) {
            int c = c0 + ty + 8 * i;
            float g = p0[c], be = p0[CC + c], m = p0[2 * CC + c], va = p0[3 * CC + c];
            float inv = g / sqrtf(va + 1e-5f);
            float sh = be - m * inv;
            size_t base = ((size_t)b * CC + c) * LLv + n0 + tx;
            float v = 0.f;
#pragma unroll
            for (int t = 0; t < TT; ++t) {
                float xv = x[base + (size_t)t * NNv] * inv + sh;
                v += (xv - v) / 1.5f;
                float sp = (v >= 1.f) ? 1.f : 0.f;
                tile[t][ty + 8 * i][tx] = sp;
                v = (v >= 1.f) ? 0.f : v;
            }
        }
        __syncthreads();
#pragma unroll
        for (int t = 0; t < TT; ++t)
#pragma unroll
            for (int i = 0; i < 4; ++i) {
                int l = t * NNv + n0 + ty + 8 * i;
                xqT[((size_t)b * LLv + l) * CC + c0 + tx] =
                    __float2half_rn(tile[t][tx][ty + 8 * i]);
            }
        return;
    }
    if (bid >= WSPLIT_BLOCKS) {
        int rb = bid - WSPLIT_BLOCKS;
        int slot = rb >> 3;
        int Cdim = (slot == 5) ? 2048 : 512;
        int c = (rb & 7) * 256 + threadIdx.x;
        if (c >= Cdim) return;
        const float* p = (slot == 0) ? p0 : (slot == 1) ? p1 : (slot == 2) ? p2 :
                         (slot == 3) ? p3 : (slot == 4) ? p4 : p5;
        float g = p[c], be = p[Cdim + c], m = p[2 * Cdim + c], va = p[3 * Cdim + c];
        float inv = g / sqrtf(va + 1e-5f);
        float sh = be - m * inv;
        if (slot == 5) sh += fc1b[c] * inv;
        scale[slot * 2048 + c] = inv;
        shift[slot * 2048 + c] = sh;
        return;
    }
    int i = bid * 256 + threadIdx.x;
    const float* src; __half *dhi, *dlo;
    if (i < 3 * SZ) {
        int seg = i / SZ, j = i - seg * SZ;
        src = (seg == 0) ? qw + j : (seg == 1) ? kw + j : vw + j;
        dhi = wqkv + seg * SZ + j; dlo = wqkv + 3 * SZ + seg * SZ + j;
    } else if (i < 4 * SZ) {
        int j = i - 3 * SZ;
        src = pw + j; dhi = wp + j; dlo = wp + SZ + j;
    } else if (i < 4 * SZ + SZH) {
        int j = i - 4 * SZ;
        src = f1 + j; dhi = wf1 + j; dlo = wf1 + SZH + j;
    } else {
        int j = i - 4 * SZ - SZH;
        src = f2 + j; dhi = wf2 + j; dlo = wf2 + SZH + j;
    }
    float xv = *src;
    __half h = __float2half_rn(xv);
    *dhi = h;
    *dlo = __float2half_rn(xv - __half2float(h));
}

// -------------------- LIF + BN -> transposed fp16 spikes (mlp input) --------
__global__ void lif_tr_k(const float* __restrict__ in, __half* __restrict__ outT,
                         const float* __restrict__ scale, const float* __restrict__ shift,
                         int Cdim) {
    __shared__ float tile[TT][32][33];
    int b = blockIdx.z, c0 = blockIdx.y * 32, n0 = blockIdx.x * 32;
    int tx = threadIdx.x, ty = threadIdx.y;
#pragma unroll
    for (int i = 0; i < 4; ++i) {
        int c = c0 + ty + 8 * i;
        float sc = scale ? scale[c] : 1.f;
        float sh = shift ? shift[c] : 0.f;
        size_t base = ((size_t)b * Cdim + c) * LLv + n0 + tx;
        float v = 0.f;
#pragma unroll
        for (int t = 0; t < TT; ++t) {
            float xv = in[base + (size_t)t * NNv] * sc + sh;
            v += (xv - v) / 1.5f;
            float sp = (v >= 1.f) ? 1.f : 0.f;
            tile[t][ty + 8 * i][tx] = sp;
            v = (v >= 1.f) ? 0.f : v;
        }
    }
    __syncthreads();
#pragma unroll
    for (int t = 0; t < TT; ++t)
#pragma unroll
        for (int i = 0; i < 4; ++i) {
            int l = t * NNv + n0 + ty + 8 * i;
            outT[((size_t)b * LLv + l) * Cdim + c0 + tx] =
                __float2half_rn(tile[t][tx][ty + 8 * i]);
        }
}

// ================= 256-thr GEMM engine ======================================
#define GEMM256_PREAMBLE()                                                      \
    extern __shared__ __align__(16) char smem[];                                \
    uint32_t sb = smem_u32(smem);                                               \
    int tid = threadIdx.x;                                                      \
    int lane = tid & 31, w = tid >> 5;                                          \
    int wm = w & 1, wn = w >> 1;                                                \
    int sub = lane >> 3, lrow = lane & 7;                                       \
    float acc[4][8][4];                                                         \
    _Pragma("unroll")                                                           \
    for (int i = 0; i < 4; ++i)                                                 \
        _Pragma("unroll")                                                       \
        for (int j = 0; j < 8; ++j)                                             \
            _Pragma("unroll")                                                   \
            for (int r = 0; r < 4; ++r) acc[i][j][r] = 0.f;

#define ISSUE256_TMAJ(TERMSTRIDE)                                               \
    auto issue_loads = [&](int c) {                                             \
        uint32_t base = sb + (uint32_t)(c % 3) * STGB;                          \
        int k0 = c * KCB;                                                       \
        _Pragma("unroll")                                                       \
        for (int i = 0; i < 8; ++i) {                                           \
            int idx = i * 256 + tid;                                            \
            int term = idx >> 10;                                               \
            int within = idx & 1023;                                            \
            int row = within >> 3, c16 = within & 7;                            \
            uint32_t o = (uint32_t)(row * 128 + c16 * 16);                      \
            CP16(base + term * ATB + SW(o),                                     \
                 Wspl + (size_t)term * (TERMSTRIDE) +                           \
                 (size_t)(tm + row) * CC + k0 + c16 * 8);                       \
        }                                                                       \
        _Pragma("unroll")                                                       \
        for (int i = 0; i < 8; ++i) {                                           \
            int idx = i * 256 + tid;                                            \
            int ridx = idx >> 3, c16 = idx & 7;                                 \
            int t = ridx >> 6, nloc = ridx & 63;                                \
            int l = t * NNv + n0 + nloc;                                        \
            uint32_t o = (uint32_t)(ridx * 128 + c16 * 16);                     \
            CP16(base + ABB + SW(o),                                            \
                 Bt + (size_t)l * CC + k0 + c16 * 8);                           \
        }                                                                       \
        CP_COMMIT();                                                            \
    };

#define ISSUE256_PLAIN(TERMSTRIDE, CI)                                          \
    auto issue_loads = [&](int c) {                                             \
        uint32_t base = sb + (uint32_t)(c % 3) * STGB;                          \
        int k0 = c * KCB;                                                       \
        _Pragma("unroll")                                                       \
        for (int i = 0; i < 8; ++i) {                                           \
            int idx = i * 256 + tid;                                            \
            int term = idx >> 10;                                               \
            int within = idx & 1023;                                            \
            int row = within >> 3, c16 = within & 7;                            \
            uint32_t o = (uint32_t)(row * 128 + c16 * 16);                      \
            CP16(base + term * ATB + SW(o),                                     \
                 Wspl + (size_t)term * (TERMSTRIDE) +                           \
                 (size_t)(tm + row) * (CI) + k0 + c16 * 8);                     \
        }                                                                       \
        _Pragma("unroll")                                                       \
        for (int i = 0; i < 8; ++i) {                                           \
            int idx = i * 256 + tid;                                            \
            int ridx = idx >> 3, c16 = idx & 7;                                 \
            uint32_t o = (uint32_t)(ridx * 128 + c16 * 16);                     \
            CP16(base + ABB + SW(o),                                            \
                 Bt + (size_t)(tn + ridx) * (CI) + k0 + c16 * 8);               \
        }                                                                       \
        CP_COMMIT();                                                            \
    };

#define GEMM256_MAINLOOP()                                                      \
    issue_loads(0);                                                             \
    issue_loads(1);                                                             \
    for (int c = 0; c < KC; ++c) {                                              \
        uint32_t base = sb + (uint32_t)(c % 3) * STGB;                          \
        if (c < KC - 1) CP_WAIT1(); else CP_WAIT0();                            \
        __syncthreads();                                                        \
        if (c + 2 < KC) issue_loads(c + 2);                                     \
        uint32_t abase = base;                                                  \
        uint32_t bbase = base + ABB;                                            \
        _Pragma("unroll")                                                       \
        for (int ks = 0; ks < 4; ++ks) {                                        \
            uint32_t bfr[4][4];                                                 \
            _Pragma("unroll")                                                   \
            for (int t = 0; t < 4; ++t) {                                       \
                int rbase = t * 64 + wn * 16 + (sub >> 1) * 8 + lrow;           \
                uint32_t o = (uint32_t)(rbase * 128 + ks * 32 + (sub & 1) * 16);\
                ldm_x4(bfr[t][0], bfr[t][1], bfr[t][2], bfr[t][3],              \
                       bbase + SW(o));                                          \
            }                                                                   \
            _Pragma("unroll")                                                   \
            for (int term = 0; term < TERMS; ++term) {                          \
                uint32_t tb = abase + term * ATB;                               \
                uint32_t af[4][4];                                              \
                _Pragma("unroll")                                               \
                for (int mi = 0; mi < 4; ++mi) {                                \
                    int m = wm * 64 + mi * 16 + (sub & 1) * 8 + lrow;           \
                    uint32_t o = (uint32_t)(m * 128 + ks * 32 + (sub >> 1) * 16);\
                    ldm_x4(af[mi][0], af[mi][1], af[mi][2], af[mi][3],          \
                           tb + SW(o));                                         \
                }                                                               \
                _Pragma("unroll")                                               \
                for (int mi = 0; mi < 4; ++mi)                                  \
                    _Pragma("unroll")                                           \
                    for (int nj = 0; nj < 8; ++nj)                              \
                        mma16816(acc[mi][nj], af[mi][0], af[mi][1], af[mi][2],  \
                                 af[mi][3], bfr[nj >> 1][(nj & 1) * 2],         \
                                 bfr[nj >> 1][(nj & 1) * 2 + 1]);               \
            }                                                                   \
        }                                                                       \
    }

// -------------------- fused qkv GEMM + BN + LIF -> skv fp16 -----------------
__global__ void __launch_bounds__(256, 1) gemm_qkv_k(
    const __half* __restrict__ Wspl, const __half* __restrict__ BT,
    __half* __restrict__ out, const float* __restrict__ scale,
    const float* __restrict__ shift) {

    GEMM256_PREAMBLE();
    int b = blockIdx.z;
    int tm = blockIdx.y * MT;
    int n0 = blockIdx.x * 64;
    const __half* Bt = BT + (size_t)b * LLv * CC;
    const int KC = CC / KCB;   // 8
    ISSUE256_TMAJ((size_t)CQKV * CC);
    GEMM256_MAINLOOP();

#pragma unroll
    for (int mi = 0; mi < 4; ++mi) {
#pragma unroll
        for (int h = 0; h < 2; ++h) {
            int co = tm + wm * 64 + mi * 16 + h * 8 + (lane >> 2);
            int sidx = ((co >> 9) << 11) | (co & 511);
            float scv = scale[sidx], shv = shift[sidx];
            __half* op = out + ((size_t)b * CQKV + co) * LLv;
#pragma unroll
            for (int uh = 0; uh < 2; ++uh) {
                float v0 = 0.f, v1 = 0.f;
#pragma unroll
                for (int t = 0; t < 4; ++t) {
                    int nj = t * 2 + uh;
                    float x0 = acc[mi][nj][h * 2 + 0] * scv + shv;
                    float x1 = acc[mi][nj][h * 2 + 1] * scv + shv;
                    v0 += (x0 - v0) / 1.5f;
                    float s0 = (v0 >= 1.f) ? 1.f : 0.f; v0 = (v0 >= 1.f) ? 0.f : v0;
                    v1 += (x1 - v1) / 1.5f;
                    float s1 = (v1 >= 1.f) ? 1.f : 0.f; v1 = (v1 >= 1.f) ? 0.f : v1;
                    int l = t * NNv + n0 + wn * 16 + uh * 8 + (lane & 3) * 2;
                    *(__half2*)(op + l) = __floats2half2_rn(s0, s1);
                }
            }
        }
    }
}

// -------------------- fused fc1 GEMM + BN + LIF -> s2T fp16 -----------------
__global__ void __launch_bounds__(256, 1) gemm_fc1_k(
    const __half* __restrict__ Wspl, const __half* __restrict__ BT,
    __half* __restrict__ s2T, const float* __restrict__ scale,
    const float* __restrict__ shift) {

    GEMM256_PREAMBLE();
    int b = blockIdx.z;
    int tm = blockIdx.y * MT;
    int n0 = blockIdx.x * 64;
    const __half* Bt = BT + (size_t)b * LLv * CC;
    const int KC = CC / KCB;   // 8
    ISSUE256_TMAJ((size_t)HIDN * CC);
    GEMM256_MAINLOOP();

    __syncthreads();
    __half* st = (__half*)smem;
#pragma unroll
    for (int mi = 0; mi < 4; ++mi) {
#pragma unroll
        for (int h = 0; h < 2; ++h) {
            int col = wm * 64 + mi * 16 + h * 8 + (lane >> 2);
            int co = tm + col;
            float scv = scale[co], shv = shift[co];
#pragma unroll
            for (int uh = 0; uh < 2; ++uh) {
                float v0 = 0.f, v1 = 0.f;
#pragma unroll
                for (int t = 0; t < 4; ++t) {
                    int nj = t * 2 + uh;
                    float x0 = acc[mi][nj][h * 2 + 0] * scv + shv;
                    float x1 = acc[mi][nj][h * 2 + 1] * scv + shv;
                    v0 += (x0 - v0) / 1.5f;
                    float s0 = (v0 >= 1.f) ? 1.f : 0.f; v0 = (v0 >= 1.f) ? 0.f : v0;
                    v1 += (x1 - v1) / 1.5f;
                    float s1 = (v1 >= 1.f) ? 1.f : 0.f; v1 = (v1 >= 1.f) ? 0.f : v1;
                    int ridx = t * 64 + wn * 16 + uh * 8 + (lane & 3) * 2;
                    st[ridx * 128 + col] = __float2half_rn(s0);
                    st[(ridx + 1) * 128 + col] = __float2half_rn(s1);
                }
            }
        }
    }
    __syncthreads();
    for (int i = tid; i < 256 * 16; i += 256) {
        int row = i >> 4, ch = i & 15;
        int t = row >> 6, nloc = row & 63;
        int l = t * NNv + n0 + nloc;
        uint4 v = *(uint4*)&st[row * 128 + ch * 8];
        *(uint4*)(s2T + ((size_t)b * LLv + l) * HIDN + tm + ch * 8) = v;
    }
}

// -------------------- fc2 GEMM (256-thr, Ci=2048) + bias + residual ---------
__global__ void __launch_bounds__(256, 1) gemm_fc2_k(
    const __half* __restrict__ Wspl, const __half* __restrict__ BT,
    float* __restrict__ out, const float* __restrict__ bias,
    const float* __restrict__ resid) {

    GEMM256_PREAMBLE();
    int b = blockIdx.z;
    int tm = blockIdx.y * MT;
    int tn = blockIdx.x * 256;
    const __half* Bt = BT + (size_t)b * LLv * HIDN;
    const int KC = HIDN / KCB;   // 32
    ISSUE256_PLAIN((size_t)CC * HIDN, HIDN);
    GEMM256_MAINLOOP();

#pragma unroll
    for (int mi = 0; mi < 4; ++mi) {
#pragma unroll
        for (int h = 0; h < 2; ++h) {
            int co = tm + wm * 64 + mi * 16 + h * 8 + (lane >> 2);
            float shv = bias[co];
            float* op = out + ((size_t)b * CC + co) * LLv + tn;
            const float* rp = resid + ((size_t)b * CC + co) * LLv + tn;
#pragma unroll
            for (int nj = 0; nj < 8; ++nj) {
                int col = (nj >> 1) * 64 + wn * 16 + (nj & 1) * 8 + (lane & 3) * 2;
                float2 rv = *(const float2*)(rp + col);
                float2 o;
                o.x = acc[mi][nj][h * 2 + 0] + shv + rv.x;
                o.y = acc[mi][nj][h * 2 + 1] + shv + rv.y;
                *(float2*)(op + col) = o;
            }
        }
    }
}

// ================= 128-thr GEMM (proj) ======================================
#define GEMM_MAINLOOP()                                                         \
    issue_loads(0);                                                             \
    issue_loads(1);                                                             \
    for (int c = 0; c < KC; ++c) {                                              \
        uint32_t base = sb + (uint32_t)(c % NSTAGE) * STAGE_BYTES;              \
        if (c < KC - 1) CP_WAIT1(); else CP_WAIT0();                            \
        __syncthreads();                                                        \
        if (c + 2 < KC) issue_loads(c + 2);                                     \
        uint32_t abase = base;                                                  \
        uint32_t bbase = base + A_BYTES;                                        \
        _Pragma("unroll")                                                       \
        for (int ks = 0; ks < 2; ++ks) {                                        \
            uint32_t bfr[4][4];                                                 \
            _Pragma("unroll")                                                   \
            for (int ni = 0; ni < 4; ++ni) {                                    \
                int n = wn * 64 + ni * 16 + (sub >> 1) * 8 + lrow;              \
                uint32_t o = (uint32_t)(n * 64 + ks * 32 + (sub & 1) * 16);     \
                ldm_x4(bfr[ni][0], bfr[ni][1], bfr[ni][2], bfr[ni][3],          \
                       bbase + SW(o));                                          \
            }                                                                   \
            _Pragma("unroll")                                                   \
            for (int term = 0; term < TERMS; ++term) {                          \
                uint32_t tb = abase + term * A_TERM_BYTES;                      \
                uint32_t af[4][4];                                              \
                _Pragma("unroll")                                               \
                for (int mi = 0; mi < 4; ++mi) {                                \
                    int m = wm * 64 + mi * 16 + (sub & 1) * 8 + lrow;           \
                    uint32_t o = (uint32_t)(m * 64 + ks * 32 + (sub >> 1) * 16);\
                    ldm_x4(af[mi][0], af[mi][1], af[mi][2], af[mi][3],          \
                           tb + SW(o));                                         \
                }                                                               \
                _Pragma("unroll")                                               \
                for (int mi = 0; mi < 4; ++mi)                                  \
                    _Pragma("unroll")                                           \
                    for (int nj = 0; nj < 8; ++nj)                              \
                        mma16816(acc[mi][nj], af[mi][0], af[mi][1], af[mi][2],  \
                                 af[mi][3], bfr[nj >> 1][(nj & 1) * 2],         \
                                 bfr[nj >> 1][(nj & 1) * 2 + 1]);               \
            }                                                                   \
        }                                                                       \
    }

__global__ void __launch_bounds__(128, 2) gemm_mma_k(
    const __half* __restrict__ Wspl, const __half* __restrict__ BT,
    float* __restrict__ out, const float* __restrict__ scale, const float* __restrict__ shift,
    const float* __restrict__ resid, int Co, int Ci) {

    extern __shared__ __align__(16) char smem[];
    uint32_t sb = smem_u32(smem);
    int tid = threadIdx.x;
    int lane = tid & 31, w = tid >> 5;
    int wm = w & 1, wn = w >> 1;
    int sub = lane >> 3, lrow = lane & 7;
    float acc[4][8][4];
#pragma unroll
    for (int i = 0; i < 4; ++i)
#pragma unroll
        for (int j = 0; j < 8; ++j)
#pragma unroll
            for (int r = 0; r < 4; ++r) acc[i][j][r] = 0.f;

    int b = blockIdx.z;
    int tm = blockIdx.y * MT;
    int tn = blockIdx.x * NTP;
    const __half* Bt = BT + (size_t)b * LLv * Ci;
    const size_t termstride = (size_t)Co * Ci;
    const int KC = Ci / KCH;

    auto issue_loads = [&](int c) {
        uint32_t base = sb + (uint32_t)(c % NSTAGE) * STAGE_BYTES;
        int k0 = c * KCH;
#pragma unroll
        for (int i = 0; i < 8; ++i) {
            int idx = i * 128 + tid;
            int term = idx >> 9;
            int within = idx & 511;
            int row = within >> 2, c16 = within & 3;
            uint32_t o = (uint32_t)(row * 64 + c16 * 16);
            CP16(base + term * A_TERM_BYTES + SW(o),
                 Wspl + (size_t)term * termstride + (size_t)(tm + row) * Ci + k0 + c16 * 8);
        }
#pragma unroll
        for (int i = 0; i < 4; ++i) {
            int idx = i * 128 + tid;
            int ridx = idx >> 2, c16 = idx & 3;
            uint32_t o = (uint32_t)(ridx * 64 + c16 * 16);
            CP16(base + A_BYTES + SW(o),
                 Bt + (size_t)(tn + ridx) * Ci + k0 + c16 * 8);
        }
        CP_COMMIT();
    };

    GEMM_MAINLOOP();

#pragma unroll
    for (int mi = 0; mi < 4; ++mi) {
#pragma unroll
        for (int h = 0; h < 2; ++h) {
            int co = tm + wm * 64 + mi * 16 + h * 8 + (lane >> 2);
            float scv = scale ? scale[co] : 1.f;
            float shv = shift ? shift[co] : 0.f;
            float* op = out + ((size_t)b * Co + co) * LLv + tn;
            const float* rp = resid ? resid + ((size_t)b * Co + co) * LLv + tn : nullptr;
#pragma unroll
            for (int nj = 0; nj < 8; ++nj) {
                int col = wn * 64 + nj * 8 + (lane & 3) * 2;
                float2 o;
                o.x = acc[mi][nj][h * 2 + 0] * scv + shv;
                o.y = acc[mi][nj][h * 2 + 1] * scv + shv;
                if (rp) {
                    float2 rv = *(const float2*)(rp + col);
                    o.x += rv.x; o.y += rv.y;
                }
                *(float2*)(op + col) = o;
            }
        }
    }
}

// -------------------- kv partials via tensor cores --------------------------
__global__ void __launch_bounds__(128, 2) kv_mma_k(
    const __half* __restrict__ skv, float* __restrict__ Mp) {
    __shared__ __align__(16) char smem[2 * 16384];
    uint32_t sb = smem_u32(smem);
    int tid = threadIdx.x;
    int lane = tid & 31, w = tid >> 5;
    int wm = w & 1, wn = w >> 1;
    int sub = lane >> 3, lrow = lane & 7;
    int bh = blockIdx.x, spl = blockIdx.y;
    int b = bh >> 3, h = bh & 7;
    const __half* K = skv + ((size_t)b * CQKV + 512 + h * HD) * LLv;
    const __half* V = skv + ((size_t)b * CQKV + 1024 + h * HD) * LLv;
    int lbeg = spl * (LLv / KVSPL);
    const int NCH = (LLv / KVSPL) / 64;

    float acc[2][4][4];
#pragma unroll
    for (int i = 0; i < 2; ++i)
#pragma unroll
        for (int j = 0; j < 4; ++j)
#pragma unroll
            for (int r = 0; r < 4; ++r) acc[i][j][r] = 0.f;

    auto issue = [&](int c) {
        uint32_t base = sb + (uint32_t)(c & 1) * 16384;
        int l0 = lbeg + c * 64;
#pragma unroll
        for (int i = 0; i < 8; ++i) {
            int idx = i * 128 + tid;
            int op = idx >> 9;
            int within = idx & 511;
            int row = within >> 3, c16 = within & 7;
            uint32_t o = (uint32_t)(row * 128 + c16 * 16);
            const __half* src = (op ? V : K) + (size_t)row * LLv + l0 + c16 * 8;
            CP16(base + op * 8192 + SW(o), src);
        }
        CP_COMMIT();
    };

    issue(0);
    issue(1);
    for (int c = 0; c < NCH; ++c) {
        uint32_t base = sb + (uint32_t)(c & 1) * 16384;
        if (c < NCH - 1) CP_WAIT1(); else CP_WAIT0();
        __syncthreads();
        uint32_t kbase = base, vbase = base + 8192;
#pragma unroll
        for (int ks = 0; ks < 4; ++ks) {
            uint32_t bfr[2][4];
#pragma unroll
            for (int ni = 0; ni < 2; ++ni) {
                int n = wn * 32 + ni * 16 + (sub >> 1) * 8 + lrow;
                uint32_t o = (uint32_t)(n * 128 + ks * 32 + (sub & 1) * 16);
                ldm_x4(bfr[ni][0], bfr[ni][1], bfr[ni][2], bfr[ni][3], vbase + SW(o));
            }
            uint32_t af[2][4];
#pragma unroll
            for (int mi = 0; mi < 2; ++mi) {
                int m = wm * 32 + mi * 16 + (sub & 1) * 8 + lrow;
                uint32_t o = (uint32_t)(m * 128 + ks * 32 + (sub >> 1) * 16);
                ldm_x4(af[mi][0], af[mi][1], af[mi][2], af[mi][3], kbase + SW(o));
            }
#pragma unroll
            for (int mi = 0; mi < 2; ++mi)
#pragma unroll
                for (int nj = 0; nj < 4; ++nj)
                    mma16816(acc[mi][nj], af[mi][0], af[mi][1], af[mi][2], af[mi][3],
                             bfr[nj >> 1][(nj & 1) * 2], bfr[nj >> 1][(nj & 1) * 2 + 1]);
        }
        __syncthreads();
        if (c + 2 < NCH) issue(c + 2);
    }

    float* Mo = Mp + ((size_t)spl * 32 + bh) * (HD * HD);
#pragma unroll
    for (int mi = 0; mi < 2; ++mi)
#pragma unroll
        for (int hh = 0; hh < 2; ++hh) {
            int j = wm * 32 + mi * 16 + hh * 8 + (lane >> 2);
#pragma unroll
            for (int nj = 0; nj < 4; ++nj) {
                int jp = wn * 32 + nj * 8 + (lane & 3) * 2;
                float2 o; o.x = acc[mi][nj][hh * 2 + 0]; o.y = acc[mi][nj][hh * 2 + 1];
                *(float2*)&Mo[j * HD + jp] = o;
            }
        }
}

// -------------------- reduce kv partials -> M^T fp16 ------------------------
__global__ void __launch_bounds__(256) red_k(const float* __restrict__ Mp,
                                             __half* __restrict__ Mt) {
    int bh = blockIdx.x;
    __shared__ float Ms[64 * 65];
    for (int idx = threadIdx.x; idx < HD * HD; idx += 256) {
        int j = idx >> 6, jp = idx & 63;
        float s = 0.f;
#pragma unroll
        for (int sp = 0; sp < KVSPL; ++sp)
            s += Mp[((size_t)sp * 32 + bh) * (HD * HD) + idx];
        Ms[j * 65 + jp] = s;
    }
    __syncthreads();
    for (int idx = threadIdx.x; idx < HD * HD; idx += 256) {
        int jp = idx >> 6, j = idx & 63;        // output [jp][j]
        Mt[(size_t)bh * (HD * HD) + idx] = __float2half_rn(Ms[j * 65 + jp]);
    }
}

// -------------------- qm on tensor cores: so = spike(Q^T @ M) ---------------
// per CTA: 64 l x 64 jp tile for one bh. A[l][j] = Q[j][l] via ldmatrix.trans;
// B[jp][j] = Mt. Integer-exact.
__global__ void __launch_bounds__(128) qm_mma_k(
    const __half* __restrict__ skv, const __half* __restrict__ Mt,
    __half* __restrict__ soT) {
    __shared__ __align__(16) char smem[16384];   // Qs 8KB | Ms 8KB
    uint32_t sb = smem_u32(smem);
    int tid = threadIdx.x;
    int lane = tid & 31, w = tid >> 5;
    int wm = w & 1, wn = w >> 1;          // 2x2 warps: wm over l, wn over jp
    int sub = lane >> 3, lrow = lane & 7;
    int bh = blockIdx.y;
    int b = bh >> 3, h = bh & 7;
    int l0 = blockIdx.x * 64;
    const __half* Qg = skv + ((size_t)b * CQKV + h * HD) * LLv;

#pragma unroll
    for (int i = 0; i < 2; ++i) {
        int idx = i * 128 + tid;              // 256 chunks each
        int row = idx >> 2, c16 = idx & 3;
        uint32_t o = (uint32_t)(row * 128 + c16 * 16);
        CP16(sb + SW(o), Qg + (size_t)row * LLv + l0 + c16 * 8);
        CP16(sb + 8192 + SW(o), Mt + (size_t)bh * (HD * HD) + row * 64 + c16 * 8);
    }
    CP_COMMIT();
    CP_WAIT0();
    __syncthreads();

    float acc[2][4][4];
#pragma unroll
    for (int i = 0; i < 2; ++i)
#pragma unroll
        for (int j = 0; j < 4; ++j)
#pragma unroll
            for (int r = 0; r < 4; ++r) acc[i][j][r] = 0.f;

#pragma unroll
    for (int ks = 0; ks < 4; ++ks) {
        uint32_t bfr[2][4];
#pragma unroll
        for (int ni = 0; ni < 2; ++ni) {      // B from Ms [jp][j]
            int n = wn * 32 + ni * 16 + (sub >> 1) * 8 + lrow;
            uint32_t o = (uint32_t)(n * 128 + ks * 32 + (sub & 1) * 16);
            ldm_x4(bfr[ni][0], bfr[ni][1], bfr[ni][2], bfr[ni][3],
                   sb + 8192 + SW(o));
        }
        uint32_t af[2][4];
#pragma unroll
        for (int mi = 0; mi < 2; ++mi) {      // A from Qs [j][l] via trans
            int jrow = ks * 16 + (sub >> 1) * 8 + lrow;
            int lcol = wm * 32 + mi * 16 + (sub & 1) * 8;
            uint32_t o = (uint32_t)(jrow * 128 + lcol * 2);
            ldm_x4t(af[mi][0], af[mi][1], af[mi][2], af[mi][3], sb + SW(o));
        }
#pragma unroll
        for (int mi = 0; mi < 2; ++mi)
#pragma unroll
            for (int nj = 0; nj < 4; ++nj)
                mma16816(acc[mi][nj], af[mi][0], af[mi][1], af[mi][2], af[mi][3],
                         bfr[nj >> 1][(nj & 1) * 2], bfr[nj >> 1][(nj & 1) * 2 + 1]);
    }

    // epilogue: spike threshold, write soT [b][l][h*64+jp]
#pragma unroll
    for (int mi = 0; mi < 2; ++mi)
#pragma unroll
        for (int hh = 0; hh < 2; ++hh) {
            int l = l0 + wm * 32 + mi * 16 + hh * 8 + (lane >> 2);
            __half* O = soT + ((size_t)b * LLv + l) * CC + h * HD;
#pragma unroll
            for (int nj = 0; nj < 4; ++nj) {
                int jp = wn * 32 + nj * 8 + (lane & 3) * 2;
                float o0 = acc[mi][nj][hh * 2 + 0] * 0.125f;
                float o1 = acc[mi][nj][hh * 2 + 1] * 0.125f;
                float s0 = ((o0 / 1.5f - 1.f) >= 0.f) ? 1.f : 0.f;
                float s1 = ((o1 / 1.5f - 1.f) >= 0.f) ? 1.f : 0.f;
                *(__half2*)(O + jp) = __floats2half2_rn(s0, s1);
            }
        }
}

// ---------------------------------------------------------------------------
extern "C" void kernel_launch(void* const* d_in, const int* in_sizes, int n_in,
                              void* d_out, int out_size) {
    const float* x       = (const float*)d_in[0];
    const float* attn_bn = (const float*)d_in[1];
    const float* q_w     = (const float*)d_in[2];
    const float* q_bn    = (const float*)d_in[3];
    const float* k_w     = (const float*)d_in[4];
    const float* k_bn    = (const float*)d_in[5];
    const float* v_w     = (const float*)d_in[6];
    const float* v_bn    = (const float*)d_in[7];
    const float* proj_w  = (const float*)d_in[8];
    const float* proj_b  = (const float*)d_in[9];
    const float* mlp_bn  = (const float*)d_in[10];
    const float* fc1_w   = (const float*)d_in[11];
    const float* fc1_b   = (const float*)d_in[12];
    const float* fc1_bn  = (const float*)d_in[13];
    const float* fc2_w   = (const float*)d_in[14];
    const float* fc2_b   = (const float*)d_in[15];
    float* out = (float*)d_out;

    float *x1, *Mp, *scale, *shift;
    __half *skv, *Mt, *xqT, *soT, *s2T, *w;
    cudaGetSymbolAddress((void**)&skv, g_skv);
    cudaGetSymbolAddress((void**)&x1,  g_x1);
    cudaGetSymbolAddress((void**)&Mp,  g_Mp);
    cudaGetSymbolAddress((void**)&Mt,  g_Mt);
    cudaGetSymbolAddress((void**)&scale, g_scale);
    cudaGetSymbolAddress((void**)&shift, g_shift);
    cudaGetSymbolAddress((void**)&xqT, g_xqT);
    cudaGetSymbolAddress((void**)&soT, g_soT);
    cudaGetSymbolAddress((void**)&s2T, g_s2T);
    cudaGetSymbolAddress((void**)&w,   g_w);

    cudaFuncSetAttribute(gemm_mma_k, cudaFuncAttributeMaxDynamicSharedMemorySize, DYN_SMEM);
    cudaFuncSetAttribute(gemm_qkv_k, cudaFuncAttributeMaxDynamicSharedMemorySize, DSMB);
    cudaFuncSetAttribute(gemm_fc1_k, cudaFuncAttributeMaxDynamicSharedMemorySize, DSMB);
    cudaFuncSetAttribute(gemm_fc2_k, cudaFuncAttributeMaxDynamicSharedMemorySize, DSMB);

    __half* wqkv = w;                       // [2][1536][512]
    __half* wp   = w + 6 * (size_t)SZ;      // [2][512][512]
    __half* wf1  = w + 8 * (size_t)SZ;      // [2][2048][512]
    __half* wf2  = wf1 + 2 * (size_t)SZH;   // [2][512][2048]

    // prologue: weight splits + BN folds + attn-input LIF (one launch)
    prep_all<<<WSPLIT_BLOCKS + BN_BLOCKS + LIF_BLOCKS, 256>>>(
        q_w, k_w, v_w, proj_w, fc1_w, fc2_w, wqkv, wp, wf1, wf2,
        attn_bn, q_bn, k_bn, v_bn, mlp_bn, fc1_bn, fc1_b, scale, shift,
        x, xqT);

    // fused q/k/v GEMM + BN + LIF -> skv spikes fp16 [B,1536,L]
    gemm_qkv_k<<<dim3(8, 12, 4), 256, DSMB>>>(wqkv, xqT, skv,
                                              scale + 2048, shift + 2048);

    // attention: kv partials (tensor cores) -> reduce -> qm (tensor cores)
    kv_mma_k<<<dim3(32, KVSPL), 128>>>(skv, Mp);
    red_k<<<32, 256>>>(Mp, Mt);
    qm_mma_k<<<dim3(32, 32), 128>>>(skv, Mt, soT);

    // proj + residual -> x1
    gemm_mma_k<<<dim3(16, 4, 4), 128, DYN_SMEM>>>(wp, soT, x1, nullptr, proj_b, x, CC, CC);

    // MLP: BN+LIF -> xqT, fc1 fused -> s2T fp16, fc2 + bias + residual -> out
    lif_tr_k<<<dim3(16, 16, BB), dim3(32, 8)>>>(x1, xqT, scale + 4 * 2048,
                                                shift + 4 * 2048, CC);
    gemm_fc1_k<<<dim3(8, 16, 4), 256, DSMB>>>(wf1, xqT, s2T,
                                              scale + 5 * 2048, shift + 5 * 2048);
    gemm_fc2_k<<<dim3(8, 4, 4), 256, DSMB>>>(wf2, s2T, out, fc2_b, x1);
}